// round 11
// baseline (speedup 1.0000x reference)
#include <cuda_runtime.h>
#include <math.h>

#define NUM_CITIES 88
#define NC4        22              // 88 / 4 float4 column groups per row
#define NUM_YEARS  6
#define N_ROWS     200000
#define UO_F4      300000          // 200000*6/4 float4 per U/OUT array (exact)

#define MAIN_BLOCK 352             // 11 warps; 352 % 22 == 0
#define MAIN_GRID  592             // 148 SMs * 4 resident blocks, one wave

// Grid-level scratch. Zero at module load; last block resets each launch so
// every graph replay starts clean.
__device__ float g_colsum[NUM_CITIES];
__device__ float g_scalar;
__device__ unsigned int g_count;

__device__ __forceinline__ void body(const float4 g, const float4 d,
                                     const float4 w,
                                     float& c0, float& c1, float& c2, float& c3,
                                     float& s)
{
    c0 += fabsf(g.x); c1 += fabsf(g.y);
    c2 += fabsf(g.z); c3 += fabsf(g.w);

    float r0 = fmaf(-w.x, d.x, g.x);
    float r1 = fmaf(-w.y, d.y, g.y);
    float r2 = fmaf(-w.z, d.z, g.z);
    float r3 = fmaf(-w.w, d.w, g.w);
    s += 100.0f * (r0*r0 + r1*r1 + r2*r2 + r3*r3);
    s += 0.01f  * (w.x*w.x + w.y*w.y + w.z*w.z + w.w*w.w);
    s += 100.0f * (fminf(g.x, 0.f) + fminf(g.y, 0.f)
                 + fminf(g.z, 0.f) + fminf(g.w, 0.f));
}

__global__ __launch_bounds__(MAIN_BLOCK)
void fused_loss_kernel(const float4* __restrict__ G4,
                       const float4* __restrict__ D4,
                       const float4* __restrict__ W4,
                       const float4* __restrict__ U4,
                       const float4* __restrict__ OUT4,
                       float* __restrict__ out)
{
    const int tid    = blockIdx.x * MAIN_BLOCK + threadIdx.x;
    const int total  = MAIN_GRID * MAIN_BLOCK;          // 208384, mult of 22
    const int lanes  = total / NC4;                     // 9472 row-lanes
    const int cg     = tid % NC4;                       // fixed column group
    const int lane   = tid / NC4;

    float c0 = 0.f, c1 = 0.f, c2 = 0.f, c3 = 0.f;       // |G| column partials
    float s  = 0.f;                                     // scalar loss partial

    // Term 1: ||U[:, :5] - out[:, :5]||_F^2, vectorized over the flat 1.2M
    // floats. Component with flat index % 6 == 5 (the unused 6th year) falls
    // on .y when q%3==1 and on .w when q%3==2 — masked branchlessly.
    for (int q = tid; q < UO_F4; q += total) {
        float4 u = __ldcs(&U4[q]);
        float4 o = __ldcs(&OUT4[q]);
        const int m  = q % 3;
        const float my = (m == 1) ? 0.0f : 1.0f;
        const float mw = (m == 2) ? 0.0f : 1.0f;
        float dx = u.x - o.x;
        float dy = (u.y - o.y) * my;
        float dz = u.z - o.z;
        float dw = (u.w - o.w) * mw;
        s += dx*dx + dy*dy + dz*dz + dw*dw;
    }

    // Main stream: G, D, w (211 MB). Thread keeps one 4-col group so |G|
    // column partials live in 4 registers; warp addresses fully contiguous.
    for (int r = lane; r < N_ROWS; r += lanes) {
        const int i = r * NC4 + cg;
        float4 g = __ldcs(&G4[i]);
        float4 d = __ldcs(&D4[i]);
        float4 w = __ldcs(&W4[i]);
        body(g, d, w, c0, c1, c2, c3, s);
    }

    // --- block-level reduction ---
    __shared__ float scol[NUM_CITIES];
    __shared__ float swarp[MAIN_BLOCK / 32];
    __shared__ unsigned int is_last;
    __shared__ float sh[128];

    if (threadIdx.x < NUM_CITIES) scol[threadIdx.x] = 0.0f;
    __syncthreads();

    // column partials: 16 threads per shared slot, once per block
    atomicAdd(&scol[cg * 4 + 0], c0);
    atomicAdd(&scol[cg * 4 + 1], c1);
    atomicAdd(&scol[cg * 4 + 2], c2);
    atomicAdd(&scol[cg * 4 + 3], c3);

    // scalar: warp shuffle reduce
    #pragma unroll
    for (int off = 16; off > 0; off >>= 1)
        s += __shfl_xor_sync(0xFFFFFFFF, s, off);
    if ((threadIdx.x & 31) == 0) swarp[threadIdx.x >> 5] = s;
    __syncthreads();

    // --- grid-level accumulation ---
    if (threadIdx.x < NUM_CITIES)
        atomicAdd(&g_colsum[threadIdx.x], scol[threadIdx.x]);
    if (threadIdx.x == 0) {
        float bs = 0.f;
        #pragma unroll
        for (int wv = 0; wv < MAIN_BLOCK / 32; wv++) bs += swarp[wv];
        atomicAdd(&g_scalar, bs);
    }

    // --- last-block finalize (threadFenceReduction pattern) ---
    __threadfence();
    __syncthreads();
    if (threadIdx.x == 0)
        is_last = (atomicAdd(&g_count, 1u) == (unsigned)(gridDim.x - 1));
    __syncthreads();
    if (!is_last) return;

    __threadfence();   // acquire: all blocks' atomics visible

    int t = threadIdx.x;
    if (t < 128) {
        float v = 0.0f;
        if (t < NUM_CITIES) {
            v = logf(*((volatile float*)&g_colsum[t]));
            *((volatile float*)&g_colsum[t]) = 0.0f;   // reset for next replay
        }
        sh[t] = v;
    }
    __syncthreads();
    #pragma unroll
    for (int off = 64; off > 0; off >>= 1) {
        if (t < off) sh[t] += sh[t + off];
        __syncthreads();
    }
    if (t == 0) {
        float sc = *((volatile float*)&g_scalar);
        out[0] = sc + 1.0e-4f * sh[0];                 // stddeve^2 = 1e-4
        *((volatile float*)&g_scalar) = 0.0f;
        g_count = 0u;
    }
}

extern "C" void kernel_launch(void* const* d_in, const int* in_sizes, int n_in,
                              void* d_out, int out_size)
{
    // metadata order: G, out, U, V, D, w   (V unused by the loss)
    const float4* G4   = (const float4*)d_in[0];
    const float4* OUT4 = (const float4*)d_in[1];
    const float4* U4   = (const float4*)d_in[2];
    const float4* D4   = (const float4*)d_in[4];
    const float4* W4   = (const float4*)d_in[5];
    float* out = (float*)d_out;

    fused_loss_kernel<<<MAIN_GRID, MAIN_BLOCK>>>(G4, D4, W4, U4, OUT4, out);
}

// round 12
// speedup vs baseline: 1.0086x; 1.0086x over previous
#include <cuda_runtime.h>
#include <math.h>

#define NUM_CITIES 88
#define NC4        22              // 88 / 4 float4 column groups per row
#define NUM_YEARS  6
#define N_ROWS     200000
#define UO_F4      300000          // 200000*6/4 float4 per U/OUT array (exact)

#define MAIN_BLOCK 352             // 11 warps; 352 % 22 == 0
#define MAIN_GRID  592             // 148 SMs * 4 resident blocks, one wave
#define TOTAL_THR  (MAIN_GRID * MAIN_BLOCK)   // 208384, multiple of 22

// Grid-level scratch. Zero at module load; last block resets each launch so
// every graph replay starts clean.
__device__ float g_colsum[NUM_CITIES];
__device__ float g_scalar;
__device__ unsigned int g_count;

__device__ __forceinline__ void body(const float4 g, const float4 d,
                                     const float4 w,
                                     float& c0, float& c1, float& c2, float& c3,
                                     float& s)
{
    c0 += fabsf(g.x); c1 += fabsf(g.y);
    c2 += fabsf(g.z); c3 += fabsf(g.w);

    float r0 = fmaf(-w.x, d.x, g.x);
    float r1 = fmaf(-w.y, d.y, g.y);
    float r2 = fmaf(-w.z, d.z, g.z);
    float r3 = fmaf(-w.w, d.w, g.w);
    s += 100.0f * (r0*r0 + r1*r1 + r2*r2 + r3*r3);
    s += 0.01f  * (w.x*w.x + w.y*w.y + w.z*w.z + w.w*w.w);
    s += 100.0f * (fminf(g.x, 0.f) + fminf(g.y, 0.f)
                 + fminf(g.z, 0.f) + fminf(g.w, 0.f));
}

// U/OUT squared-diff for one float4, masking the unused 6th-year component:
// flat index % 6 == 5 lands on .y when q%3==1, on .w when q%3==2.
__device__ __forceinline__ void ubody(const float4 u, const float4 o,
                                      int q, float& s)
{
    const int m  = q % 3;
    const float my = (m == 1) ? 0.0f : 1.0f;
    const float mw = (m == 2) ? 0.0f : 1.0f;
    float dx = u.x - o.x;
    float dy = (u.y - o.y) * my;
    float dz = u.z - o.z;
    float dw = (u.w - o.w) * mw;
    s += dx*dx + dy*dy + dz*dz + dw*dw;
}

__global__ __launch_bounds__(MAIN_BLOCK)
void fused_loss_kernel(const float4* __restrict__ G4,
                       const float4* __restrict__ D4,
                       const float4* __restrict__ W4,
                       const float4* __restrict__ U4,
                       const float4* __restrict__ OUT4,
                       float* __restrict__ out)
{
    const int tid   = blockIdx.x * MAIN_BLOCK + threadIdx.x;
    const int lanes = TOTAL_THR / NC4;                 // 9472 row-lanes
    const int cg    = threadIdx.x % NC4;               // fixed (352%22==0)
    const int lane  = tid / NC4;

    float c0 = 0.f, c1 = 0.f, c2 = 0.f, c3 = 0.f;      // |G| column partials
    float s  = 0.f;                                    // scalar loss partial

    // ---- First main iteration FUSED with the entire U-term ----
    // All loads below are independent: up to 7 LDG.128 in flight per thread
    // from cycle ~0. No serial U-prologue.
    {
        const int i0 = lane * NC4 + cg;                // lane < 9472 < N_ROWS
        float4 g0 = __ldcs(&G4[i0]);
        float4 d0 = __ldcs(&D4[i0]);
        float4 w0 = __ldcs(&W4[i0]);

        const int  q1   = tid + TOTAL_THR;             // second U chunk
        const bool has2 = (q1 < UO_F4);                // tid < 91616
        float4 ua = __ldcs(&U4[tid]);
        float4 oa = __ldcs(&OUT4[tid]);
        float4 ub = make_float4(0.f, 0.f, 0.f, 0.f);
        float4 ob = ub;
        if (has2) { ub = __ldcs(&U4[q1]); ob = __ldcs(&OUT4[q1]); }

        body(g0, d0, w0, c0, c1, c2, c3, s);
        ubody(ua, oa, tid, s);
        if (has2) ubody(ub, ob, q1, s);
    }

    // ---- Main stream: G, D, w (211 MB), iterations 2..~22 ----
    for (int r = lane + lanes; r < N_ROWS; r += lanes) {
        const int i = r * NC4 + cg;
        float4 g = __ldcs(&G4[i]);
        float4 d = __ldcs(&D4[i]);
        float4 w = __ldcs(&W4[i]);
        body(g, d, w, c0, c1, c2, c3, s);
    }

    // --- block-level reduction ---
    __shared__ float scol[NUM_CITIES];
    __shared__ float swarp[MAIN_BLOCK / 32];
    __shared__ unsigned int is_last;
    __shared__ float sh[128];

    if (threadIdx.x < NUM_CITIES) scol[threadIdx.x] = 0.0f;
    __syncthreads();

    // column partials: 16 threads per shared slot, once per block
    atomicAdd(&scol[cg * 4 + 0], c0);
    atomicAdd(&scol[cg * 4 + 1], c1);
    atomicAdd(&scol[cg * 4 + 2], c2);
    atomicAdd(&scol[cg * 4 + 3], c3);

    // scalar: warp shuffle reduce
    #pragma unroll
    for (int off = 16; off > 0; off >>= 1)
        s += __shfl_xor_sync(0xFFFFFFFF, s, off);
    if ((threadIdx.x & 31) == 0) swarp[threadIdx.x >> 5] = s;
    __syncthreads();

    // --- grid-level accumulation ---
    if (threadIdx.x < NUM_CITIES)
        atomicAdd(&g_colsum[threadIdx.x], scol[threadIdx.x]);
    if (threadIdx.x == 0) {
        float bs = 0.f;
        #pragma unroll
        for (int wv = 0; wv < MAIN_BLOCK / 32; wv++) bs += swarp[wv];
        atomicAdd(&g_scalar, bs);
    }

    // --- last-block finalize (threadFenceReduction pattern) ---
    __threadfence();
    __syncthreads();
    if (threadIdx.x == 0)
        is_last = (atomicAdd(&g_count, 1u) == (unsigned)(gridDim.x - 1));
    __syncthreads();
    if (!is_last) return;

    __threadfence();   // acquire: all blocks' atomics visible

    int t = threadIdx.x;
    if (t < 128) {
        float v = 0.0f;
        if (t < NUM_CITIES) {
            v = logf(*((volatile float*)&g_colsum[t]));
            *((volatile float*)&g_colsum[t]) = 0.0f;   // reset for next replay
        }
        sh[t] = v;
    }
    __syncthreads();
    #pragma unroll
    for (int off = 64; off > 0; off >>= 1) {
        if (t < off) sh[t] += sh[t + off];
        __syncthreads();
    }
    if (t == 0) {
        float sc = *((volatile float*)&g_scalar);
        out[0] = sc + 1.0e-4f * sh[0];                 // stddeve^2 = 1e-4
        *((volatile float*)&g_scalar) = 0.0f;
        g_count = 0u;
    }
}

extern "C" void kernel_launch(void* const* d_in, const int* in_sizes, int n_in,
                              void* d_out, int out_size)
{
    // metadata order: G, out, U, V, D, w   (V unused by the loss)
    const float4* G4   = (const float4*)d_in[0];
    const float4* OUT4 = (const float4*)d_in[1];
    const float4* U4   = (const float4*)d_in[2];
    const float4* D4   = (const float4*)d_in[4];
    const float4* W4   = (const float4*)d_in[5];
    float* out = (float*)d_out;

    fused_loss_kernel<<<MAIN_GRID, MAIN_BLOCK>>>(G4, D4, W4, U4, OUT4, out);
}